// round 7
// baseline (speedup 1.0000x reference)
#include <cuda_runtime.h>

#define Dc 128
#define XROW 132
#define TE 64
#define NTHREADS 256
#define NN 50000
#define EE 500000
#define MAXT 10.0f

typedef unsigned long long ull;

// Scratch (device globals: no allocation allowed)
__device__ float g_agg[(size_t)NN * Dc];
__device__ float g_csum[(size_t)NN * 3];
__device__ float g_deg[NN];

__device__ __forceinline__ float sigmoidf_(float x) { return 1.f / (1.f + __expf(-x)); }
__device__ __forceinline__ float siluf_(float x) { return x / (1.f + __expf(-x)); }
__device__ __forceinline__ float clampt_(float x) { return fminf(fmaxf(x, -MAXT), MAXT); }

// ---- packed fp32 helpers (Blackwell f32x2 path) ----
__device__ __forceinline__ ull pk2(float x) {
    ull r; asm("mov.b64 %0, {%1, %1};" : "=l"(r) : "f"(x)); return r;
}
__device__ __forceinline__ void fma2(ull& d, ull a, ull b) {
    asm("fma.rn.f32x2 %0, %1, %2, %0;" : "+l"(d) : "l"(a), "l"(b));
}
__device__ __forceinline__ float2 up2(ull v) {
    float2 r; asm("mov.b64 {%0, %1}, %2;" : "=f"(r.x), "=f"(r.y) : "l"(v)); return r;
}

__global__ void zero_kernel() {
    const int total = NN * Dc + NN * 3 + NN;
    for (int i = blockIdx.x * blockDim.x + threadIdx.x; i < total; i += gridDim.x * blockDim.x) {
        if (i < NN * Dc) g_agg[i] = 0.f;
        else if (i < NN * Dc + NN * 3) g_csum[i - NN * Dc] = 0.f;
        else g_deg[i - NN * Dc - NN * 3] = 0.f;
    }
}

// Packed GEMM: acc[4 edges][4 f32x2-pairs] += Xs[le_base+e][:] @ W[:, fb..fb+7]
// W row-major [rows x 128]; weight float4s reinterpreted as native f32x2 pairs.
__device__ __forceinline__ void gemm128p(const float* __restrict__ W,
                                         const float (*Xs)[XROW],
                                         int le_base, int fb, ull acc[4][4]) {
#pragma unroll 1
    for (int k = 0; k < Dc; k += 4) {
        ulonglong2 w[4][2];
#pragma unroll
        for (int j = 0; j < 4; j++) {
            const ulonglong2* wr = (const ulonglong2*)(W + (size_t)(k + j) * Dc + fb);
            w[j][0] = __ldg(wr);
            w[j][1] = __ldg(wr + 1);
        }
#pragma unroll
        for (int e = 0; e < 4; e++) {
            float4 x = *(const float4*)&Xs[le_base + e][k];
            ull b0 = pk2(x.x), b1 = pk2(x.y), b2 = pk2(x.z), b3 = pk2(x.w);
            fma2(acc[e][0], b0, w[0][0].x); fma2(acc[e][1], b0, w[0][0].y);
            fma2(acc[e][2], b0, w[0][1].x); fma2(acc[e][3], b0, w[0][1].y);
            fma2(acc[e][0], b1, w[1][0].x); fma2(acc[e][1], b1, w[1][0].y);
            fma2(acc[e][2], b1, w[1][1].x); fma2(acc[e][3], b1, w[1][1].y);
            fma2(acc[e][0], b2, w[2][0].x); fma2(acc[e][1], b2, w[2][0].y);
            fma2(acc[e][2], b2, w[2][1].x); fma2(acc[e][3], b2, w[2][1].y);
            fma2(acc[e][0], b3, w[3][0].x); fma2(acc[e][1], b3, w[3][0].y);
            fma2(acc[e][2], b3, w[3][1].x); fma2(acc[e][3], b3, w[3][1].y);
        }
    }
}

// reduce across the 16 feature-lanes of an el-group (offsets 8,4,2,1 stay in-group)
__device__ __forceinline__ float redu16(float p) {
#pragma unroll
    for (int off = 8; off > 0; off >>= 1) p += __shfl_xor_sync(0xffffffffu, p, off);
    return p;
}

__global__ void __launch_bounds__(NTHREADS) edge_kernel(
    const float* __restrict__ h, const int* __restrict__ ei, const float* __restrict__ coord,
    const float* __restrict__ We1, const float* __restrict__ be1,
    const float* __restrict__ We2, const float* __restrict__ be2,
    const float* __restrict__ Watt, const float* __restrict__ batt,
    const float* __restrict__ Wc1, const float* __restrict__ bc1,
    const float* __restrict__ Wc2, float* __restrict__ edge_out) {
    __shared__ float Xs[TE][XROW];
    __shared__ int sRow[TE];
    __shared__ int sCol[TE];
    __shared__ float sRad[TE];
    __shared__ float sCd[TE][3];

    const int tid = threadIdx.x;
    const int lane = tid & 31;
    const int warp = tid >> 5;
    const int fl = lane & 15;
    const int el = lane >> 4;
    const int fb = fl * 8;
    const int le_base = warp * 8 + el * 4;
    const int base = blockIdx.x * TE;

    if (tid < TE) {
        int ee = base + tid;
        if (ee >= EE) ee = EE - 1;  // clamp; writes masked later
        int r = ei[ee];
        int c = ei[EE + ee];
        sRow[tid] = r;
        sCol[tid] = c;
        float dx = coord[r * 3 + 0] - coord[c * 3 + 0];
        float dy = coord[r * 3 + 1] - coord[c * 3 + 1];
        float dz = coord[r * 3 + 2] - coord[c * 3 + 2];
        sCd[tid][0] = dx; sCd[tid][1] = dy; sCd[tid][2] = dz;
        sRad[tid] = dx * dx + dy * dy + dz * dz;
    }
    __syncthreads();

    // ---- stage h[row] tile; GEMM We1 rows [0,128) ----
    for (int i = tid; i < TE * 32; i += NTHREADS) {
        int e = i >> 5, l = i & 31;
        *(float4*)&Xs[e][l * 4] = __ldg((const float4*)&h[(size_t)sRow[e] * Dc + l * 4]);
    }
    __syncthreads();

    ull acc[4][4];
#pragma unroll
    for (int e = 0; e < 4; e++)
#pragma unroll
        for (int p = 0; p < 4; p++) acc[e][p] = 0ull;
    gemm128p(We1, Xs, le_base, fb, acc);
    __syncthreads();

    // ---- stage h[col] tile; GEMM We1 rows [128,256) ----
    for (int i = tid; i < TE * 32; i += NTHREADS) {
        int e = i >> 5, l = i & 31;
        *(float4*)&Xs[e][l * 4] = __ldg((const float4*)&h[(size_t)sCol[e] * Dc + l * 4]);
    }
    __syncthreads();
    gemm128p(We1 + 128 * Dc, Xs, le_base, fb, acc);

    // radial term (We1 row 256) + bias + SiLU
    float a[4][8];
    {
        const ulonglong2* wrr = (const ulonglong2*)(We1 + (size_t)256 * Dc + fb);
        ulonglong2 wr0 = __ldg(wrr), wr1 = __ldg(wrr + 1);
        float4 ba = __ldg((const float4*)&be1[fb]);
        float4 bb = __ldg((const float4*)&be1[fb + 4]);
#pragma unroll
        for (int e = 0; e < 4; e++) {
            ull br = pk2(sRad[le_base + e]);
            fma2(acc[e][0], br, wr0.x); fma2(acc[e][1], br, wr0.y);
            fma2(acc[e][2], br, wr1.x); fma2(acc[e][3], br, wr1.y);
            float2 p0 = up2(acc[e][0]), p1 = up2(acc[e][1]);
            float2 p2 = up2(acc[e][2]), p3 = up2(acc[e][3]);
            a[e][0] = siluf_(p0.x + ba.x); a[e][1] = siluf_(p0.y + ba.y);
            a[e][2] = siluf_(p1.x + ba.z); a[e][3] = siluf_(p1.y + ba.w);
            a[e][4] = siluf_(p2.x + bb.x); a[e][5] = siluf_(p2.y + bb.y);
            a[e][6] = siluf_(p3.x + bb.z); a[e][7] = siluf_(p3.y + bb.w);
        }
    }
    __syncthreads();
#pragma unroll
    for (int e = 0; e < 4; e++) {
        *(float4*)&Xs[le_base + e][fb]     = make_float4(a[e][0], a[e][1], a[e][2], a[e][3]);
        *(float4*)&Xs[le_base + e][fb + 4] = make_float4(a[e][4], a[e][5], a[e][6], a[e][7]);
    }
    __syncthreads();

    // ---- e2 = silu(e1 @ We2 + be2); att; edge_feat = e2 * att ----
#pragma unroll
    for (int e = 0; e < 4; e++)
#pragma unroll
        for (int p = 0; p < 4; p++) acc[e][p] = 0ull;
    gemm128p(We2, Xs, le_base, fb, acc);
    {
        float4 ba = __ldg((const float4*)&be2[fb]);
        float4 bb = __ldg((const float4*)&be2[fb + 4]);
        float4 wta = __ldg((const float4*)&Watt[fb]);
        float4 wtb = __ldg((const float4*)&Watt[fb + 4]);
        float batt_ = __ldg(batt);
#pragma unroll
        for (int e = 0; e < 4; e++) {
            float2 p0 = up2(acc[e][0]), p1 = up2(acc[e][1]);
            float2 p2 = up2(acc[e][2]), p3 = up2(acc[e][3]);
            a[e][0] = siluf_(p0.x + ba.x); a[e][1] = siluf_(p0.y + ba.y);
            a[e][2] = siluf_(p1.x + ba.z); a[e][3] = siluf_(p1.y + ba.w);
            a[e][4] = siluf_(p2.x + bb.x); a[e][5] = siluf_(p2.y + bb.y);
            a[e][6] = siluf_(p3.x + bb.z); a[e][7] = siluf_(p3.y + bb.w);
            float p = a[e][0] * wta.x + a[e][1] * wta.y + a[e][2] * wta.z + a[e][3] * wta.w
                    + a[e][4] * wtb.x + a[e][5] * wtb.y + a[e][6] * wtb.z + a[e][7] * wtb.w;
            p = redu16(p);
            float att = sigmoidf_(p + batt_);
#pragma unroll
            for (int j = 0; j < 8; j++) a[e][j] *= att;
        }
    }
    __syncthreads();

    // ---- write edge_feat, segment_sum atomics, stage tile for coord MLP ----
#pragma unroll
    for (int e = 0; e < 4; e++) {
        int le = le_base + e;
        float4 v0 = make_float4(a[e][0], a[e][1], a[e][2], a[e][3]);
        float4 v1 = make_float4(a[e][4], a[e][5], a[e][6], a[e][7]);
        *(float4*)&Xs[le][fb]     = v0;
        *(float4*)&Xs[le][fb + 4] = v1;
        int ee = base + le;
        if (ee < EE) {
            *(float4*)&edge_out[(size_t)ee * Dc + fb]     = v0;
            *(float4*)&edge_out[(size_t)ee * Dc + fb + 4] = v1;
            float* ag = &g_agg[(size_t)sRow[le] * Dc + fb];
            atomicAdd(ag + 0, v0.x); atomicAdd(ag + 1, v0.y);
            atomicAdd(ag + 2, v0.z); atomicAdd(ag + 3, v0.w);
            atomicAdd(ag + 4, v1.x); atomicAdd(ag + 5, v1.y);
            atomicAdd(ag + 6, v1.z); atomicAdd(ag + 7, v1.w);
        }
    }
    __syncthreads();

    // ---- coord MLP: cw = silu(edge_feat @ Wc1 + bc1) @ Wc2 ----
#pragma unroll
    for (int e = 0; e < 4; e++)
#pragma unroll
        for (int p = 0; p < 4; p++) acc[e][p] = 0ull;
    gemm128p(Wc1, Xs, le_base, fb, acc);
    {
        float4 ba = __ldg((const float4*)&bc1[fb]);
        float4 bb = __ldg((const float4*)&bc1[fb + 4]);
        float4 w2a = __ldg((const float4*)&Wc2[fb]);
        float4 w2b = __ldg((const float4*)&Wc2[fb + 4]);
#pragma unroll
        for (int e = 0; e < 4; e++) {
            float2 p0 = up2(acc[e][0]), p1 = up2(acc[e][1]);
            float2 p2 = up2(acc[e][2]), p3 = up2(acc[e][3]);
            float c0 = siluf_(p0.x + ba.x), c1 = siluf_(p0.y + ba.y);
            float c2 = siluf_(p1.x + ba.z), c3 = siluf_(p1.y + ba.w);
            float c4 = siluf_(p2.x + bb.x), c5 = siluf_(p2.y + bb.y);
            float c6 = siluf_(p3.x + bb.z), c7 = siluf_(p3.y + bb.w);
            float p = c0 * w2a.x + c1 * w2a.y + c2 * w2a.z + c3 * w2a.w
                    + c4 * w2b.x + c5 * w2b.y + c6 * w2b.z + c7 * w2b.w;
            float cw = redu16(p);  // all 16 lanes of the group hold cw
            int le = le_base + e;
            int ee = base + le;
            if (ee < EE) {
                if (fl < 3) {
                    float t = clampt_(sCd[le][fl] * cw);
                    atomicAdd(&g_csum[(size_t)sRow[le] * 3 + fl], t);
                } else if (fl == 3) {
                    atomicAdd(&g_deg[sRow[le]], 1.f);
                }
            }
        }
    }
}

__global__ void __launch_bounds__(NTHREADS) node_kernel(
    const float* __restrict__ h, const float* __restrict__ coord,
    const float* __restrict__ Wn1, const float* __restrict__ bn1,
    const float* __restrict__ Wn2, const float* __restrict__ bn2,
    float* __restrict__ hout, float* __restrict__ cout) {
    __shared__ float Xs[TE][XROW];
    const int tid = threadIdx.x;
    const int lane = tid & 31;
    const int warp = tid >> 5;
    const int fl = lane & 15;
    const int el = lane >> 4;
    const int fb = fl * 8;
    const int le_base = warp * 8 + el * 4;
    const int base = blockIdx.x * TE;

    // stage h tile (clamped)
    for (int i = tid; i < TE * 32; i += NTHREADS) {
        int n = base + (i >> 5);
        if (n >= NN) n = NN - 1;
        *(float4*)&Xs[i >> 5][(i & 31) * 4] = __ldg((const float4*)&h[(size_t)n * Dc + (i & 31) * 4]);
    }
    __syncthreads();

    ull acc[4][4];
#pragma unroll
    for (int e = 0; e < 4; e++)
#pragma unroll
        for (int p = 0; p < 4; p++) acc[e][p] = 0ull;
    gemm128p(Wn1, Xs, le_base, fb, acc);  // rows [0,128): h part
    __syncthreads();

    // stage agg tile
    for (int i = tid; i < TE * 32; i += NTHREADS) {
        int n = base + (i >> 5);
        if (n >= NN) n = NN - 1;
        *(float4*)&Xs[i >> 5][(i & 31) * 4] = *(const float4*)&g_agg[(size_t)n * Dc + (i & 31) * 4];
    }
    __syncthreads();
    gemm128p(Wn1 + 128 * Dc, Xs, le_base, fb, acc);  // rows [128,256): agg part

    float a[4][8];
    {
        float4 ba = __ldg((const float4*)&bn1[fb]);
        float4 bb = __ldg((const float4*)&bn1[fb + 4]);
#pragma unroll
        for (int e = 0; e < 4; e++) {
            float2 p0 = up2(acc[e][0]), p1 = up2(acc[e][1]);
            float2 p2 = up2(acc[e][2]), p3 = up2(acc[e][3]);
            a[e][0] = siluf_(p0.x + ba.x); a[e][1] = siluf_(p0.y + ba.y);
            a[e][2] = siluf_(p1.x + ba.z); a[e][3] = siluf_(p1.y + ba.w);
            a[e][4] = siluf_(p2.x + bb.x); a[e][5] = siluf_(p2.y + bb.y);
            a[e][6] = siluf_(p3.x + bb.z); a[e][7] = siluf_(p3.y + bb.w);
        }
    }
    __syncthreads();
#pragma unroll
    for (int e = 0; e < 4; e++) {
        *(float4*)&Xs[le_base + e][fb]     = make_float4(a[e][0], a[e][1], a[e][2], a[e][3]);
        *(float4*)&Xs[le_base + e][fb + 4] = make_float4(a[e][4], a[e][5], a[e][6], a[e][7]);
    }
    __syncthreads();

#pragma unroll
    for (int e = 0; e < 4; e++)
#pragma unroll
        for (int p = 0; p < 4; p++) acc[e][p] = 0ull;
    gemm128p(Wn2, Xs, le_base, fb, acc);
    {
        float4 ba = __ldg((const float4*)&bn2[fb]);
        float4 bb = __ldg((const float4*)&bn2[fb + 4]);
#pragma unroll
        for (int e = 0; e < 4; e++) {
            int n = base + le_base + e;
            if (n < NN) {
                float2 p0 = up2(acc[e][0]), p1 = up2(acc[e][1]);
                float2 p2 = up2(acc[e][2]), p3 = up2(acc[e][3]);
                float4 h0 = __ldg((const float4*)&h[(size_t)n * Dc + fb]);
                float4 h1 = __ldg((const float4*)&h[(size_t)n * Dc + fb + 4]);
                float4 o0, o1;
                o0.x = h0.x + p0.x + ba.x; o0.y = h0.y + p0.y + ba.y;
                o0.z = h0.z + p1.x + ba.z; o0.w = h0.w + p1.y + ba.w;
                o1.x = h1.x + p2.x + bb.x; o1.y = h1.y + p2.y + bb.y;
                o1.z = h1.z + p3.x + bb.z; o1.w = h1.w + p3.y + bb.w;
                *(float4*)&hout[(size_t)n * Dc + fb]     = o0;
                *(float4*)&hout[(size_t)n * Dc + fb + 4] = o1;
            }
        }
    }

    // coord output: 64 nodes x 3 components
    if (tid < TE * 3) {
        int e = tid / 3, c = tid % 3;
        int n = base + e;
        if (n < NN) {
            float d = fmaxf(g_deg[n], 1.f);
            float v = clampt_(g_csum[(size_t)n * 3 + c] / d);
            cout[(size_t)n * 3 + c] = coord[(size_t)n * 3 + c] + v;
        }
    }
}

extern "C" void kernel_launch(void* const* d_in, const int* in_sizes, int n_in,
                              void* d_out, int out_size) {
    const float* h     = (const float*)d_in[0];
    const int*   ei    = (const int*)d_in[1];   // jax x64 disabled -> int32
    const float* coord = (const float*)d_in[2];
    const float* We1   = (const float*)d_in[3];
    const float* be1   = (const float*)d_in[4];
    const float* We2   = (const float*)d_in[5];
    const float* be2   = (const float*)d_in[6];
    const float* Watt  = (const float*)d_in[7];
    const float* batt  = (const float*)d_in[8];
    const float* Wc1   = (const float*)d_in[9];
    const float* bc1   = (const float*)d_in[10];
    const float* Wc2   = (const float*)d_in[11];
    const float* Wn1   = (const float*)d_in[12];
    const float* bn1   = (const float*)d_in[13];
    const float* Wn2   = (const float*)d_in[14];
    const float* bn2   = (const float*)d_in[15];

    float* out  = (float*)d_out;
    float* hout = out;                                   // [N,128]
    float* cout = out + (size_t)NN * Dc;                 // [N,3]
    float* eout = cout + (size_t)NN * 3;                 // [E,128]

    zero_kernel<<<2048, 256>>>();
    edge_kernel<<<(EE + TE - 1) / TE, NTHREADS>>>(h, ei, coord, We1, be1, We2, be2,
                                                  Watt, batt, Wc1, bc1, Wc2, eout);
    node_kernel<<<(NN + TE - 1) / TE, NTHREADS>>>(h, coord, Wn1, bn1, Wn2, bn2, hout, cout);
}

// round 12
// speedup vs baseline: 3.0218x; 3.0218x over previous
#include <cuda_runtime.h>
#include <cuda_bf16.h>
#include <cstdint>

#define Dc 128
#define TE 64
#define NTHREADS 256
#define NN 50000
#define EE 500000
#define MAXT 10.0f
#define XPAD 136   // bf16 per row: 272B stride -> conflict-free ldmatrix

// Scratch (device globals: no allocation allowed)
__device__ float g_agg[(size_t)NN * Dc];
__device__ float g_csum[(size_t)NN * 3];
__device__ float g_deg[NN];
// Weight fragments: 56 kk-chunks x 16 ntiles x 32 lanes x 16B (hi0,hi1,lo0,lo1)
__device__ uint4 g_wfrag[56 * 16 * 32];

__device__ __forceinline__ float sigmoidf_(float x) { return 1.f / (1.f + __expf(-x)); }
__device__ __forceinline__ float siluf_(float x) { return x / (1.f + __expf(-x)); }
__device__ __forceinline__ float clampt_(float x) { return fminf(fmaxf(x, -MAXT), MAXT); }

__device__ __forceinline__ unsigned pkb(__nv_bfloat16 a, __nv_bfloat16 b) {
    __nv_bfloat162 t(a, b);
    return *(unsigned*)&t;
}
__device__ __forceinline__ void splitbf(float x, __nv_bfloat16& h, __nv_bfloat16& l) {
    h = __float2bfloat16_rn(x);
    l = __float2bfloat16_rn(x - __bfloat162float(h));
}

__device__ __forceinline__ void mma16816(float c[4], const unsigned a[4], unsigned b0, unsigned b1) {
    asm volatile(
        "mma.sync.aligned.m16n8k16.row.col.f32.bf16.bf16.f32 "
        "{%0,%1,%2,%3}, {%4,%5,%6,%7}, {%8,%9}, {%0,%1,%2,%3};"
        : "+f"(c[0]), "+f"(c[1]), "+f"(c[2]), "+f"(c[3])
        : "r"(a[0]), "r"(a[1]), "r"(a[2]), "r"(a[3]), "r"(b0), "r"(b1));
}
__device__ __forceinline__ void ldsm4(unsigned r[4], const void* p) {
    uint32_t sa = (uint32_t)__cvta_generic_to_shared(p);
    asm volatile("ldmatrix.sync.aligned.m8n8.x4.shared.b16 {%0,%1,%2,%3}, [%4];"
                 : "=r"(r[0]), "=r"(r[1]), "=r"(r[2]), "=r"(r[3]) : "r"(sa));
}

__global__ void zero_kernel() {
    const int total = NN * Dc + NN * 3 + NN;
    for (int i = blockIdx.x * blockDim.x + threadIdx.x; i < total; i += gridDim.x * blockDim.x) {
        if (i < NN * Dc) g_agg[i] = 0.f;
        else if (i < NN * Dc + NN * 3) g_csum[i - NN * Dc] = 0.f;
        else g_deg[i - NN * Dc - NN * 3] = 0.f;
    }
}

// Pre-split weights into bf16 hi/lo, fragment-major layout.
// kk chunks: We1 rows0-255 -> kk 0..15 | We2 -> 16..23 | Wc1 -> 24..31 | Wn1 -> 32..47 | Wn2 -> 48..55
__global__ void prep_weights(const float* __restrict__ We1, const float* __restrict__ We2,
                             const float* __restrict__ Wc1, const float* __restrict__ Wn1,
                             const float* __restrict__ Wn2) {
    int idx = blockIdx.x * blockDim.x + threadIdx.x;
    if (idx >= 56 * 16 * 32) return;
    int lane = idx & 31;
    int f = idx >> 5;          // fragment id
    int kk_t = f >> 4;         // 0..55
    int nn_g = f & 15;         // 0..15
    const float* W; int kk;
    if (kk_t < 16)      { W = We1; kk = kk_t; }
    else if (kk_t < 24) { W = We2; kk = kk_t - 16; }
    else if (kk_t < 32) { W = Wc1; kk = kk_t - 24; }
    else if (kk_t < 48) { W = Wn1; kk = kk_t - 32; }
    else                { W = Wn2; kk = kk_t - 48; }
    int n  = nn_g * 8 + (lane >> 2);
    int k0 = kk * 16 + (lane & 3) * 2;
    float v0 = W[(size_t)(k0 + 0) * Dc + n];
    float v1 = W[(size_t)(k0 + 1) * Dc + n];
    float v2 = W[(size_t)(k0 + 8) * Dc + n];
    float v3 = W[(size_t)(k0 + 9) * Dc + n];
    __nv_bfloat16 h0, l0, h1, l1, h2, l2, h3, l3;
    splitbf(v0, h0, l0); splitbf(v1, h1, l1); splitbf(v2, h2, l2); splitbf(v3, h3, l3);
    g_wfrag[f * 32 + lane] = make_uint4(pkb(h0, h1), pkb(h2, h3), pkb(l0, l1), pkb(l2, l3));
}

// One 64x128 += X(64xK=128) @ W(128x128) pass via split-bf16 MMA.
// Warp (rt,ct): rows 16*rt.., cols 64*ct..  c[8][4] fragment accumulators.
__device__ __forceinline__ void gemm_pass(float c[8][4],
                                          const __nv_bfloat16 (*Xh)[XPAD],
                                          const __nv_bfloat16 (*Xl)[XPAD],
                                          int wbase, int rt, int ct, int lane) {
    const int arow = rt * 16 + (lane & 15);
    const int acol8 = (lane & 16) >> 1;  // 0 or 8
#pragma unroll 1
    for (int kk = 0; kk < 8; kk++) {
        unsigned ah[4], al[4];
        ldsm4(ah, &Xh[arow][kk * 16 + acol8]);
        ldsm4(al, &Xl[arow][kk * 16 + acol8]);
        const uint4* wp = &g_wfrag[((size_t)(wbase + kk) * 16 + ct * 8) * 32 + lane];
#pragma unroll
        for (int nn = 0; nn < 8; nn++) {
            uint4 w = __ldg(wp + nn * 32);
            mma16816(c[nn], ah, w.x, w.y);  // hi*hi
            mma16816(c[nn], ah, w.z, w.w);  // hi*lo
            mma16816(c[nn], al, w.x, w.y);  // lo*hi
        }
    }
}

__global__ void __launch_bounds__(NTHREADS) edge_kernel(
    const float* __restrict__ h, const int* __restrict__ ei, const float* __restrict__ coord,
    const float* __restrict__ We1, const float* __restrict__ be1,
    const float* __restrict__ be2, const float* __restrict__ Watt, const float* __restrict__ batt,
    const float* __restrict__ bc1, const float* __restrict__ Wc2,
    float* __restrict__ edge_out) {
    __shared__ __nv_bfloat16 Xh[TE][XPAD];
    __shared__ __nv_bfloat16 Xl[TE][XPAD];
    __shared__ int sRow[TE];
    __shared__ int sCol[TE];
    __shared__ float sRad[TE];
    __shared__ float sCd[TE][3];
    __shared__ float sPart[2][TE];

    const int tid = threadIdx.x;
    const int lane = tid & 31;
    const int warp = tid >> 5;
    const int rt = warp >> 1;            // row tile (16 edges)
    const int ct = warp & 1;             // col half (64 feats)
    const int g = lane >> 2;             // fragment row group
    const int tig = lane & 3;            // col pair
    const int row0 = rt * 16 + g;        // fragment rows: row0 and row0+8
    const int base = blockIdx.x * TE;

    if (tid < TE) {
        int ee = base + tid;
        if (ee >= EE) ee = EE - 1;  // clamp; writes masked later
        int r = ei[ee];
        int c = ei[EE + ee];
        sRow[tid] = r;
        sCol[tid] = c;
        float dx = coord[r * 3 + 0] - coord[c * 3 + 0];
        float dy = coord[r * 3 + 1] - coord[c * 3 + 1];
        float dz = coord[r * 3 + 2] - coord[c * 3 + 2];
        sCd[tid][0] = dx; sCd[tid][1] = dy; sCd[tid][2] = dz;
        sRad[tid] = dx * dx + dy * dy + dz * dz;
    }
    __syncthreads();

    float c[8][4];
#pragma unroll
    for (int nn = 0; nn < 8; nn++)
#pragma unroll
        for (int j = 0; j < 4; j++) c[nn][j] = 0.f;

    // ---- stage h[row] (bf16 hi/lo), GEMM We1 rows [0,128) ----
    for (int i = tid; i < TE * 32; i += NTHREADS) {
        int e = i >> 5, l4 = (i & 31) * 4;
        float4 v = __ldg((const float4*)&h[(size_t)sRow[e] * Dc + l4]);
        __nv_bfloat16 h0, l0, h1, l1, h2, l2, h3, l3;
        splitbf(v.x, h0, l0); splitbf(v.y, h1, l1); splitbf(v.z, h2, l2); splitbf(v.w, h3, l3);
        *(uint2*)&Xh[e][l4] = make_uint2(pkb(h0, h1), pkb(h2, h3));
        *(uint2*)&Xl[e][l4] = make_uint2(pkb(l0, l1), pkb(l2, l3));
    }
    __syncthreads();
    gemm_pass(c, Xh, Xl, 0, rt, ct, lane);
    __syncthreads();

    // ---- stage h[col], GEMM We1 rows [128,256) ----
    for (int i = tid; i < TE * 32; i += NTHREADS) {
        int e = i >> 5, l4 = (i & 31) * 4;
        float4 v = __ldg((const float4*)&h[(size_t)sCol[e] * Dc + l4]);
        __nv_bfloat16 h0, l0, h1, l1, h2, l2, h3, l3;
        splitbf(v.x, h0, l0); splitbf(v.y, h1, l1); splitbf(v.z, h2, l2); splitbf(v.w, h3, l3);
        *(uint2*)&Xh[e][l4] = make_uint2(pkb(h0, h1), pkb(h2, h3));
        *(uint2*)&Xl[e][l4] = make_uint2(pkb(l0, l1), pkb(l2, l3));
    }
    __syncthreads();
    gemm_pass(c, Xh, Xl, 8, rt, ct, lane);
    __syncthreads();  // all reads of Xh/Xl done before epilogue rewrites

    // ---- epilogue1: + radial*We1[256] + be1, SiLU; restage as next A ----
    {
        float rad0 = sRad[row0], rad1 = sRad[row0 + 8];
#pragma unroll
        for (int nn = 0; nn < 8; nn++) {
            int col = ct * 64 + nn * 8 + tig * 2;
            float2 wr = __ldg((const float2*)&We1[(size_t)256 * Dc + col]);
            float2 b1 = __ldg((const float2*)&be1[col]);
            c[nn][0] = siluf_(c[nn][0] + rad0 * wr.x + b1.x);
            c[nn][1] = siluf_(c[nn][1] + rad0 * wr.y + b1.y);
            c[nn][2] = siluf_(c[nn][2] + rad1 * wr.x + b1.x);
            c[nn][3] = siluf_(c[nn][3] + rad1 * wr.y + b1.y);
            __nv_bfloat16 h0, l0, h1, l1, h2, l2, h3, l3;
            splitbf(c[nn][0], h0, l0); splitbf(c[nn][1], h1, l1);
            splitbf(c[nn][2], h2, l2); splitbf(c[nn][3], h3, l3);
            *(unsigned*)&Xh[row0][col]     = pkb(h0, h1);
            *(unsigned*)&Xh[row0 + 8][col] = pkb(h2, h3);
            *(unsigned*)&Xl[row0][col]     = pkb(l0, l1);
            *(unsigned*)&Xl[row0 + 8][col] = pkb(l2, l3);
        }
    }
    __syncthreads();

    // ---- layer2: e2 = silu(e1@We2+be2); att; ef = e2*att ----
#pragma unroll
    for (int nn = 0; nn < 8; nn++)
#pragma unroll
        for (int j = 0; j < 4; j++) c[nn][j] = 0.f;
    gemm_pass(c, Xh, Xl, 16, rt, ct, lane);

    {
        float pA = 0.f, pB = 0.f;
#pragma unroll
        for (int nn = 0; nn < 8; nn++) {
            int col = ct * 64 + nn * 8 + tig * 2;
            float2 b2 = __ldg((const float2*)&be2[col]);
            float2 wa = __ldg((const float2*)&Watt[col]);
            c[nn][0] = siluf_(c[nn][0] + b2.x);
            c[nn][1] = siluf_(c[nn][1] + b2.y);
            c[nn][2] = siluf_(c[nn][2] + b2.x);
            c[nn][3] = siluf_(c[nn][3] + b2.y);
            pA += c[nn][0] * wa.x + c[nn][1] * wa.y;
            pB += c[nn][2] * wa.x + c[nn][3] * wa.y;
        }
        pA += __shfl_xor_sync(0xffffffffu, pA, 1); pA += __shfl_xor_sync(0xffffffffu, pA, 2);
        pB += __shfl_xor_sync(0xffffffffu, pB, 1); pB += __shfl_xor_sync(0xffffffffu, pB, 2);
        if (tig == 0) { sPart[ct][row0] = pA; sPart[ct][row0 + 8] = pB; }
    }
    __syncthreads();
    {
        float ba = __ldg(batt);
        float attA = sigmoidf_(sPart[0][row0] + sPart[1][row0] + ba);
        float attB = sigmoidf_(sPart[0][row0 + 8] + sPart[1][row0 + 8] + ba);
#pragma unroll
        for (int nn = 0; nn < 8; nn++) {
            c[nn][0] *= attA; c[nn][1] *= attA;
            c[nn][2] *= attB; c[nn][3] *= attB;
        }
    }

    // ---- write edge_feat, agg atomics, restage ef as A for coord MLP ----
    {
        int r0 = sRow[row0], r1 = sRow[row0 + 8];
        int ee0 = base + row0, ee1 = base + row0 + 8;
#pragma unroll
        for (int nn = 0; nn < 8; nn++) {
            int col = ct * 64 + nn * 8 + tig * 2;
            __nv_bfloat16 h0, l0, h1, l1, h2, l2, h3, l3;
            splitbf(c[nn][0], h0, l0); splitbf(c[nn][1], h1, l1);
            splitbf(c[nn][2], h2, l2); splitbf(c[nn][3], h3, l3);
            *(unsigned*)&Xh[row0][col]     = pkb(h0, h1);
            *(unsigned*)&Xh[row0 + 8][col] = pkb(h2, h3);
            *(unsigned*)&Xl[row0][col]     = pkb(l0, l1);
            *(unsigned*)&Xl[row0 + 8][col] = pkb(l2, l3);
            if (ee0 < EE) {
                *(float2*)&edge_out[(size_t)ee0 * Dc + col] = make_float2(c[nn][0], c[nn][1]);
                atomicAdd(&g_agg[(size_t)r0 * Dc + col],     c[nn][0]);
                atomicAdd(&g_agg[(size_t)r0 * Dc + col + 1], c[nn][1]);
            }
            if (ee1 < EE) {
                *(float2*)&edge_out[(size_t)ee1 * Dc + col] = make_float2(c[nn][2], c[nn][3]);
                atomicAdd(&g_agg[(size_t)r1 * Dc + col],     c[nn][2]);
                atomicAdd(&g_agg[(size_t)r1 * Dc + col + 1], c[nn][3]);
            }
        }
    }
    __syncthreads();

    // ---- coord MLP: cw = silu(ef@Wc1+bc1) @ Wc2 ----
#pragma unroll
    for (int nn = 0; nn < 8; nn++)
#pragma unroll
        for (int j = 0; j < 4; j++) c[nn][j] = 0.f;
    gemm_pass(c, Xh, Xl, 24, rt, ct, lane);

    {
        float pA = 0.f, pB = 0.f;
#pragma unroll
        for (int nn = 0; nn < 8; nn++) {
            int col = ct * 64 + nn * 8 + tig * 2;
            float2 bc = __ldg((const float2*)&bc1[col]);
            float2 w2 = __ldg((const float2*)&Wc2[col]);
            pA += siluf_(c[nn][0] + bc.x) * w2.x + siluf_(c[nn][1] + bc.y) * w2.y;
            pB += siluf_(c[nn][2] + bc.x) * w2.x + siluf_(c[nn][3] + bc.y) * w2.y;
        }
        pA += __shfl_xor_sync(0xffffffffu, pA, 1); pA += __shfl_xor_sync(0xffffffffu, pA, 2);
        pB += __shfl_xor_sync(0xffffffffu, pB, 1); pB += __shfl_xor_sync(0xffffffffu, pB, 2);
        if (tig == 0) { sPart[ct][row0] = pA; sPart[ct][row0 + 8] = pB; }
    }
    __syncthreads();
    if (ct == 0) {
#pragma unroll
        for (int half = 0; half < 2; half++) {
            int rr = row0 + half * 8;
            int ee = base + rr;
            if (ee < EE) {
                float cw = sPart[0][rr] + sPart[1][rr];
                if (tig < 3) {
                    float t = clampt_(sCd[rr][tig] * cw);
                    atomicAdd(&g_csum[(size_t)sRow[rr] * 3 + tig], t);
                } else {
                    atomicAdd(&g_deg[sRow[rr]], 1.f);
                }
            }
        }
    }
}

__global__ void __launch_bounds__(NTHREADS) node_kernel(
    const float* __restrict__ h, const float* __restrict__ coord,
    const float* __restrict__ bn1, const float* __restrict__ bn2,
    float* __restrict__ hout, float* __restrict__ cout) {
    __shared__ __nv_bfloat16 Xh[TE][XPAD];
    __shared__ __nv_bfloat16 Xl[TE][XPAD];

    const int tid = threadIdx.x;
    const int lane = tid & 31;
    const int warp = tid >> 5;
    const int rt = warp >> 1;
    const int ct = warp & 1;
    const int g = lane >> 2;
    const int tig = lane & 3;
    const int row0 = rt * 16 + g;
    const int base = blockIdx.x * TE;

    float c[8][4];
#pragma unroll
    for (int nn = 0; nn < 8; nn++)
#pragma unroll
        for (int j = 0; j < 4; j++) c[nn][j] = 0.f;

    // stage h tile (clamped)
    for (int i = tid; i < TE * 32; i += NTHREADS) {
        int n = base + (i >> 5);
        if (n >= NN) n = NN - 1;
        int l4 = (i & 31) * 4;
        float4 v = __ldg((const float4*)&h[(size_t)n * Dc + l4]);
        __nv_bfloat16 h0, l0, h1, l1, h2, l2, h3, l3;
        splitbf(v.x, h0, l0); splitbf(v.y, h1, l1); splitbf(v.z, h2, l2); splitbf(v.w, h3, l3);
        *(uint2*)&Xh[i >> 5][l4] = make_uint2(pkb(h0, h1), pkb(h2, h3));
        *(uint2*)&Xl[i >> 5][l4] = make_uint2(pkb(l0, l1), pkb(l2, l3));
    }
    __syncthreads();
    gemm_pass(c, Xh, Xl, 32, rt, ct, lane);  // Wn1 rows [0,128): h part
    __syncthreads();

    // stage agg tile
    for (int i = tid; i < TE * 32; i += NTHREADS) {
        int n = base + (i >> 5);
        if (n >= NN) n = NN - 1;
        int l4 = (i & 31) * 4;
        float4 v = *(const float4*)&g_agg[(size_t)n * Dc + l4];
        __nv_bfloat16 h0, l0, h1, l1, h2, l2, h3, l3;
        splitbf(v.x, h0, l0); splitbf(v.y, h1, l1); splitbf(v.z, h2, l2); splitbf(v.w, h3, l3);
        *(uint2*)&Xh[i >> 5][l4] = make_uint2(pkb(h0, h1), pkb(h2, h3));
        *(uint2*)&Xl[i >> 5][l4] = make_uint2(pkb(l0, l1), pkb(l2, l3));
    }
    __syncthreads();
    gemm_pass(c, Xh, Xl, 40, rt, ct, lane);  // Wn1 rows [128,256): agg part
    __syncthreads();

    // epilogue: silu(+bn1), restage for Wn2
#pragma unroll
    for (int nn = 0; nn < 8; nn++) {
        int col = ct * 64 + nn * 8 + tig * 2;
        float2 b1 = __ldg((const float2*)&bn1[col]);
        c[nn][0] = siluf_(c[nn][0] + b1.x);
        c[nn][1] = siluf_(c[nn][1] + b1.y);
        c[nn][2] = siluf_(c[nn][2] + b1.x);
        c[nn][3] = siluf_(c[nn][3] + b1.y);
        __nv_bfloat16 h0, l0, h1, l1, h2, l2, h3, l3;
        splitbf(c[nn][0], h0, l0); splitbf(c[nn][1], h1, l1);
        splitbf(c[nn][2], h2, l2); splitbf(c[nn][3], h3, l3);
        *(unsigned*)&Xh[row0][col]     = pkb(h0, h1);
        *(unsigned*)&Xh[row0 + 8][col] = pkb(h2, h3);
        *(unsigned*)&Xl[row0][col]     = pkb(l0, l1);
        *(unsigned*)&Xl[row0 + 8][col] = pkb(l2, l3);
    }
    __syncthreads();

#pragma unroll
    for (int nn = 0; nn < 8; nn++)
#pragma unroll
        for (int j = 0; j < 4; j++) c[nn][j] = 0.f;
    gemm_pass(c, Xh, Xl, 48, rt, ct, lane);  // Wn2

    {
        int n0 = base + row0, n1 = base + row0 + 8;
#pragma unroll
        for (int nn = 0; nn < 8; nn++) {
            int col = ct * 64 + nn * 8 + tig * 2;
            float2 b2 = __ldg((const float2*)&bn2[col]);
            if (n0 < NN) {
                float2 hv = __ldg((const float2*)&h[(size_t)n0 * Dc + col]);
                *(float2*)&hout[(size_t)n0 * Dc + col] =
                    make_float2(hv.x + c[nn][0] + b2.x, hv.y + c[nn][1] + b2.y);
            }
            if (n1 < NN) {
                float2 hv = __ldg((const float2*)&h[(size_t)n1 * Dc + col]);
                *(float2*)&hout[(size_t)n1 * Dc + col] =
                    make_float2(hv.x + c[nn][2] + b2.x, hv.y + c[nn][3] + b2.y);
            }
        }
    }

    // coord output: 64 nodes x 3 components
    if (tid < TE * 3) {
        int e = tid / 3, cc = tid % 3;
        int n = base + e;
        if (n < NN) {
            float d = fmaxf(g_deg[n], 1.f);
            float v = clampt_(g_csum[(size_t)n * 3 + cc] / d);
            cout[(size_t)n * 3 + cc] = coord[(size_t)n * 3 + cc] + v;
        }
    }
}

extern "C" void kernel_launch(void* const* d_in, const int* in_sizes, int n_in,
                              void* d_out, int out_size) {
    const float* h     = (const float*)d_in[0];
    const int*   ei    = (const int*)d_in[1];   // jax x64 disabled -> int32
    const float* coord = (const float*)d_in[2];
    const float* We1   = (const float*)d_in[3];
    const float* be1   = (const float*)d_in[4];
    const float* We2   = (const float*)d_in[5];
    const float* be2   = (const float*)d_in[6];
    const float* Watt  = (const float*)d_in[7];
    const float* batt  = (const float*)d_in[8];
    const float* Wc1   = (const float*)d_in[9];
    const float* bc1   = (const float*)d_in[10];
    const float* Wc2   = (const float*)d_in[11];
    const float* Wn1   = (const float*)d_in[12];
    const float* bn1   = (const float*)d_in[13];
    const float* Wn2   = (const float*)d_in[14];
    const float* bn2   = (const float*)d_in[15];

    float* out  = (float*)d_out;
    float* hout = out;                                   // [N,128]
    float* cout = out + (size_t)NN * Dc;                 // [N,3]
    float* eout = cout + (size_t)NN * 3;                 // [E,128]

    zero_kernel<<<2048, 256>>>();
    prep_weights<<<(56 * 16 * 32 + 255) / 256, 256>>>(We1, We2, Wc1, Wn1, Wn2);
    edge_kernel<<<(EE + TE - 1) / TE, NTHREADS>>>(h, ei, coord, We1, be1,
                                                  be2, Watt, batt, bc1, Wc2, eout);
    node_kernel<<<(NN + TE - 1) / TE, NTHREADS>>>(h, coord, bn1, bn2, hout, cout);
}

// round 13
// speedup vs baseline: 4.3325x; 1.4338x over previous
#include <cuda_runtime.h>
#include <cuda_bf16.h>
#include <cstdint>

#define Dc 128
#define TE 64          // tile for pq/node kernels (256 threads)
#define TEE 32         // tile for edge kernel (128 threads)
#define NN 50000
#define EE 500000
#define MAXT 10.0f
#define XPAD 136   // bf16 per row: 272B stride -> conflict-free ldmatrix

// Scratch (device globals: no allocation allowed)
__device__ float g_agg[(size_t)NN * Dc];
__device__ float g_csum[(size_t)NN * 3];
__device__ float g_deg[NN];
__device__ float g_P[(size_t)NN * Dc];   // h @ We1[0:128]
__device__ float g_Q[(size_t)NN * Dc];   // h @ We1[128:256]
// Weight fragments: 56 kk-chunks x 16 ntiles x 32 lanes x 16B (hi0,hi1,lo0,lo1)
__device__ uint4 g_wfrag[56 * 16 * 32];

__device__ __forceinline__ float sigmoidf_(float x) { return 1.f / (1.f + __expf(-x)); }
__device__ __forceinline__ float siluf_(float x) { return x / (1.f + __expf(-x)); }
__device__ __forceinline__ float clampt_(float x) { return fminf(fmaxf(x, -MAXT), MAXT); }

__device__ __forceinline__ unsigned pkb(__nv_bfloat16 a, __nv_bfloat16 b) {
    __nv_bfloat162 t(a, b);
    return *(unsigned*)&t;
}
__device__ __forceinline__ void splitbf(float x, __nv_bfloat16& h, __nv_bfloat16& l) {
    h = __float2bfloat16_rn(x);
    l = __float2bfloat16_rn(x - __bfloat162float(h));
}

__device__ __forceinline__ void mma16816(float c[4], const unsigned a[4], unsigned b0, unsigned b1) {
    asm volatile(
        "mma.sync.aligned.m16n8k16.row.col.f32.bf16.bf16.f32 "
        "{%0,%1,%2,%3}, {%4,%5,%6,%7}, {%8,%9}, {%0,%1,%2,%3};"
        : "+f"(c[0]), "+f"(c[1]), "+f"(c[2]), "+f"(c[3])
        : "r"(a[0]), "r"(a[1]), "r"(a[2]), "r"(a[3]), "r"(b0), "r"(b1));
}
__device__ __forceinline__ void ldsm4(unsigned r[4], const void* p) {
    uint32_t sa = (uint32_t)__cvta_generic_to_shared(p);
    asm volatile("ldmatrix.sync.aligned.m8n8.x4.shared.b16 {%0,%1,%2,%3}, [%4];"
                 : "=r"(r[0]), "=r"(r[1]), "=r"(r[2]), "=r"(r[3]) : "r"(sa));
}

__global__ void zero_kernel() {
    const int total = NN * Dc + NN * 3 + NN;
    for (int i = blockIdx.x * blockDim.x + threadIdx.x; i < total; i += gridDim.x * blockDim.x) {
        if (i < NN * Dc) g_agg[i] = 0.f;
        else if (i < NN * Dc + NN * 3) g_csum[i - NN * Dc] = 0.f;
        else g_deg[i - NN * Dc - NN * 3] = 0.f;
    }
}

// Pre-split weights into bf16 hi/lo, fragment-major layout.
// kk chunks: We1 rows0-255 -> 0..15 | We2 -> 16..23 | Wc1 -> 24..31 | Wn1 -> 32..47 | Wn2 -> 48..55
__global__ void prep_weights(const float* __restrict__ We1, const float* __restrict__ We2,
                             const float* __restrict__ Wc1, const float* __restrict__ Wn1,
                             const float* __restrict__ Wn2) {
    int idx = blockIdx.x * blockDim.x + threadIdx.x;
    if (idx >= 56 * 16 * 32) return;
    int lane = idx & 31;
    int f = idx >> 5;
    int kk_t = f >> 4;
    int nn_g = f & 15;
    const float* W; int kk;
    if (kk_t < 16)      { W = We1; kk = kk_t; }
    else if (kk_t < 24) { W = We2; kk = kk_t - 16; }
    else if (kk_t < 32) { W = Wc1; kk = kk_t - 24; }
    else if (kk_t < 48) { W = Wn1; kk = kk_t - 32; }
    else                { W = Wn2; kk = kk_t - 48; }
    int n  = nn_g * 8 + (lane >> 2);
    int k0 = kk * 16 + (lane & 3) * 2;
    float v0 = W[(size_t)(k0 + 0) * Dc + n];
    float v1 = W[(size_t)(k0 + 1) * Dc + n];
    float v2 = W[(size_t)(k0 + 8) * Dc + n];
    float v3 = W[(size_t)(k0 + 9) * Dc + n];
    __nv_bfloat16 h0, l0, h1, l1, h2, l2, h3, l3;
    splitbf(v0, h0, l0); splitbf(v1, h1, l1); splitbf(v2, h2, l2); splitbf(v3, h3, l3);
    g_wfrag[f * 32 + lane] = make_uint4(pkb(h0, h1), pkb(h2, h3), pkb(l0, l1), pkb(l2, l3));
}

// One (rows x 128) += X(rows x 128) @ W(128x128) pass via split-bf16 MMA.
template <int XR>
__device__ __forceinline__ void gemm_pass(float c[8][4],
                                          const __nv_bfloat16 (*Xh)[XPAD],
                                          const __nv_bfloat16 (*Xl)[XPAD],
                                          int wbase, int rt, int ct, int lane) {
    const int arow = rt * 16 + (lane & 15);
    const int acol8 = (lane & 16) >> 1;
#pragma unroll 1
    for (int kk = 0; kk < 8; kk++) {
        unsigned ah[4], al[4];
        ldsm4(ah, &Xh[arow][kk * 16 + acol8]);
        ldsm4(al, &Xl[arow][kk * 16 + acol8]);
        const uint4* wp = &g_wfrag[((size_t)(wbase + kk) * 16 + ct * 8) * 32 + lane];
#pragma unroll
        for (int nn = 0; nn < 8; nn++) {
            uint4 w = __ldg(wp + nn * 32);
            mma16816(c[nn], ah, w.x, w.y);  // hi*hi
            mma16816(c[nn], ah, w.z, w.w);  // hi*lo
            mma16816(c[nn], al, w.x, w.y);  // lo*hi
        }
    }
}

// P = h @ We1_top, Q = h @ We1_bot (node-level: removes 10x work from edge kernel)
__global__ void __launch_bounds__(256) pq_kernel(const float* __restrict__ h) {
    __shared__ __nv_bfloat16 Xh[TE][XPAD];
    __shared__ __nv_bfloat16 Xl[TE][XPAD];
    const int tid = threadIdx.x;
    const int lane = tid & 31;
    const int warp = tid >> 5;
    const int rt = warp >> 1;
    const int ct = warp & 1;
    const int g = lane >> 2;
    const int tig = lane & 3;
    const int row0 = rt * 16 + g;
    const int base = blockIdx.x * TE;

    for (int i = tid; i < TE * 32; i += 256) {
        int n = base + (i >> 5);
        if (n >= NN) n = NN - 1;
        int l4 = (i & 31) * 4;
        float4 v = __ldg((const float4*)&h[(size_t)n * Dc + l4]);
        __nv_bfloat16 h0, l0, h1, l1, h2, l2, h3, l3;
        splitbf(v.x, h0, l0); splitbf(v.y, h1, l1); splitbf(v.z, h2, l2); splitbf(v.w, h3, l3);
        *(uint2*)&Xh[i >> 5][l4] = make_uint2(pkb(h0, h1), pkb(h2, h3));
        *(uint2*)&Xl[i >> 5][l4] = make_uint2(pkb(l0, l1), pkb(l2, l3));
    }
    __syncthreads();

    float c[8][4];
    const int n0 = base + row0, n1 = base + row0 + 8;
#pragma unroll
    for (int nn = 0; nn < 8; nn++)
#pragma unroll
        for (int j = 0; j < 4; j++) c[nn][j] = 0.f;
    gemm_pass<TE>(c, Xh, Xl, 0, rt, ct, lane);     // We1 top
#pragma unroll
    for (int nn = 0; nn < 8; nn++) {
        int col = ct * 64 + nn * 8 + tig * 2;
        if (n0 < NN) *(float2*)&g_P[(size_t)n0 * Dc + col] = make_float2(c[nn][0], c[nn][1]);
        if (n1 < NN) *(float2*)&g_P[(size_t)n1 * Dc + col] = make_float2(c[nn][2], c[nn][3]);
        c[nn][0] = c[nn][1] = c[nn][2] = c[nn][3] = 0.f;
    }
    gemm_pass<TE>(c, Xh, Xl, 8, rt, ct, lane);     // We1 bottom
#pragma unroll
    for (int nn = 0; nn < 8; nn++) {
        int col = ct * 64 + nn * 8 + tig * 2;
        if (n0 < NN) *(float2*)&g_Q[(size_t)n0 * Dc + col] = make_float2(c[nn][0], c[nn][1]);
        if (n1 < NN) *(float2*)&g_Q[(size_t)n1 * Dc + col] = make_float2(c[nn][2], c[nn][3]);
    }
}

__global__ void __launch_bounds__(128) edge_kernel(
    const int* __restrict__ ei, const float* __restrict__ coord,
    const float* __restrict__ We1, const float* __restrict__ be1,
    const float* __restrict__ be2, const float* __restrict__ Watt, const float* __restrict__ batt,
    const float* __restrict__ bc1, const float* __restrict__ Wc2,
    float* __restrict__ edge_out) {
    __shared__ __nv_bfloat16 Xh[TEE][XPAD];
    __shared__ __nv_bfloat16 Xl[TEE][XPAD];
    __shared__ int sRow[TEE];
    __shared__ float sCd[TEE][3];
    __shared__ float sPart[2][TEE];

    const int tid = threadIdx.x;
    const int lane = tid & 31;
    const int warp = tid >> 5;
    const int rt = warp >> 1;            // 2 row tiles of 16 edges
    const int ct = warp & 1;             // col half (64 feats)
    const int g = lane >> 2;
    const int tig = lane & 3;
    const int row0 = rt * 16 + g;
    const int base = blockIdx.x * TEE;

    __shared__ int sCol[TEE];
    __shared__ float sRad[TEE];
    if (tid < TEE) {
        int ee = base + tid;
        if (ee >= EE) ee = EE - 1;  // clamp; writes masked later
        int r = ei[ee];
        int c = ei[EE + ee];
        sRow[tid] = r;
        sCol[tid] = c;
        float dx = coord[r * 3 + 0] - coord[c * 3 + 0];
        float dy = coord[r * 3 + 1] - coord[c * 3 + 1];
        float dz = coord[r * 3 + 2] - coord[c * 3 + 2];
        sCd[tid][0] = dx; sCd[tid][1] = dy; sCd[tid][2] = dz;
        sRad[tid] = dx * dx + dy * dy + dz * dz;
    }
    __syncthreads();

    // ---- layer1 fused: e1 = silu(P[row] + Q[col] + rad*We1[256] + be1); split-stage ----
    for (int i = tid; i < TEE * 32; i += 128) {
        int e = i >> 5, l4 = (i & 31) * 4;
        float4 p = __ldg((const float4*)&g_P[(size_t)sRow[e] * Dc + l4]);
        float4 q = __ldg((const float4*)&g_Q[(size_t)sCol[e] * Dc + l4]);
        float4 wr = __ldg((const float4*)&We1[(size_t)256 * Dc + l4]);
        float4 b1 = __ldg((const float4*)&be1[l4]);
        float rad = sRad[e];
        float v0 = siluf_(p.x + q.x + rad * wr.x + b1.x);
        float v1 = siluf_(p.y + q.y + rad * wr.y + b1.y);
        float v2 = siluf_(p.z + q.z + rad * wr.z + b1.z);
        float v3 = siluf_(p.w + q.w + rad * wr.w + b1.w);
        __nv_bfloat16 h0, l0, h1, l1, h2, l2, h3, l3;
        splitbf(v0, h0, l0); splitbf(v1, h1, l1); splitbf(v2, h2, l2); splitbf(v3, h3, l3);
        *(uint2*)&Xh[e][l4] = make_uint2(pkb(h0, h1), pkb(h2, h3));
        *(uint2*)&Xl[e][l4] = make_uint2(pkb(l0, l1), pkb(l2, l3));
    }
    __syncthreads();

    // ---- layer2: e2 = silu(e1@We2+be2); att; ef = e2*att ----
    float c[8][4];
#pragma unroll
    for (int nn = 0; nn < 8; nn++)
#pragma unroll
        for (int j = 0; j < 4; j++) c[nn][j] = 0.f;
    gemm_pass<TEE>(c, Xh, Xl, 16, rt, ct, lane);

    {
        float pA = 0.f, pB = 0.f;
#pragma unroll
        for (int nn = 0; nn < 8; nn++) {
            int col = ct * 64 + nn * 8 + tig * 2;
            float2 b2 = __ldg((const float2*)&be2[col]);
            float2 wa = __ldg((const float2*)&Watt[col]);
            c[nn][0] = siluf_(c[nn][0] + b2.x);
            c[nn][1] = siluf_(c[nn][1] + b2.y);
            c[nn][2] = siluf_(c[nn][2] + b2.x);
            c[nn][3] = siluf_(c[nn][3] + b2.y);
            pA += c[nn][0] * wa.x + c[nn][1] * wa.y;
            pB += c[nn][2] * wa.x + c[nn][3] * wa.y;
        }
        pA += __shfl_xor_sync(0xffffffffu, pA, 1); pA += __shfl_xor_sync(0xffffffffu, pA, 2);
        pB += __shfl_xor_sync(0xffffffffu, pB, 1); pB += __shfl_xor_sync(0xffffffffu, pB, 2);
        if (tig == 0) { sPart[ct][row0] = pA; sPart[ct][row0 + 8] = pB; }
    }
    __syncthreads();
    {
        float ba = __ldg(batt);
        float attA = sigmoidf_(sPart[0][row0] + sPart[1][row0] + ba);
        float attB = sigmoidf_(sPart[0][row0 + 8] + sPart[1][row0 + 8] + ba);
#pragma unroll
        for (int nn = 0; nn < 8; nn++) {
            c[nn][0] *= attA; c[nn][1] *= attA;
            c[nn][2] *= attB; c[nn][3] *= attB;
        }
    }
    __syncthreads();  // sPart reads done before any restage races (paranoia, cheap)

    // ---- write edge_feat, agg atomics, restage ef as A for coord MLP ----
    {
        int r0 = sRow[row0], r1 = sRow[row0 + 8];
        int ee0 = base + row0, ee1 = base + row0 + 8;
#pragma unroll
        for (int nn = 0; nn < 8; nn++) {
            int col = ct * 64 + nn * 8 + tig * 2;
            __nv_bfloat16 h0, l0, h1, l1, h2, l2, h3, l3;
            splitbf(c[nn][0], h0, l0); splitbf(c[nn][1], h1, l1);
            splitbf(c[nn][2], h2, l2); splitbf(c[nn][3], h3, l3);
            *(unsigned*)&Xh[row0][col]     = pkb(h0, h1);
            *(unsigned*)&Xh[row0 + 8][col] = pkb(h2, h3);
            *(unsigned*)&Xl[row0][col]     = pkb(l0, l1);
            *(unsigned*)&Xl[row0 + 8][col] = pkb(l2, l3);
            if (ee0 < EE) {
                *(float2*)&edge_out[(size_t)ee0 * Dc + col] = make_float2(c[nn][0], c[nn][1]);
                atomicAdd(&g_agg[(size_t)r0 * Dc + col],     c[nn][0]);
                atomicAdd(&g_agg[(size_t)r0 * Dc + col + 1], c[nn][1]);
            }
            if (ee1 < EE) {
                *(float2*)&edge_out[(size_t)ee1 * Dc + col] = make_float2(c[nn][2], c[nn][3]);
                atomicAdd(&g_agg[(size_t)r1 * Dc + col],     c[nn][2]);
                atomicAdd(&g_agg[(size_t)r1 * Dc + col + 1], c[nn][3]);
            }
        }
    }
    __syncthreads();

    // ---- coord MLP: cw = silu(ef@Wc1+bc1) @ Wc2 ----
#pragma unroll
    for (int nn = 0; nn < 8; nn++)
#pragma unroll
        for (int j = 0; j < 4; j++) c[nn][j] = 0.f;
    gemm_pass<TEE>(c, Xh, Xl, 24, rt, ct, lane);

    {
        float pA = 0.f, pB = 0.f;
#pragma unroll
        for (int nn = 0; nn < 8; nn++) {
            int col = ct * 64 + nn * 8 + tig * 2;
            float2 bc = __ldg((const float2*)&bc1[col]);
            float2 w2 = __ldg((const float2*)&Wc2[col]);
            pA += siluf_(c[nn][0] + bc.x) * w2.x + siluf_(c[nn][1] + bc.y) * w2.y;
            pB += siluf_(c[nn][2] + bc.x) * w2.x + siluf_(c[nn][3] + bc.y) * w2.y;
        }
        pA += __shfl_xor_sync(0xffffffffu, pA, 1); pA += __shfl_xor_sync(0xffffffffu, pA, 2);
        pB += __shfl_xor_sync(0xffffffffu, pB, 1); pB += __shfl_xor_sync(0xffffffffu, pB, 2);
        if (tig == 0) { sPart[ct][row0] = pA; sPart[ct][row0 + 8] = pB; }
    }
    __syncthreads();
    if (ct == 0) {
#pragma unroll
        for (int half = 0; half < 2; half++) {
            int rr = row0 + half * 8;
            int ee = base + rr;
            if (ee < EE) {
                float cw = sPart[0][rr] + sPart[1][rr];
                if (tig < 3) {
                    float t = clampt_(sCd[rr][tig] * cw);
                    atomicAdd(&g_csum[(size_t)sRow[rr] * 3 + tig], t);
                } else {
                    atomicAdd(&g_deg[sRow[rr]], 1.f);
                }
            }
        }
    }
}

__global__ void __launch_bounds__(256) node_kernel(
    const float* __restrict__ h, const float* __restrict__ coord,
    const float* __restrict__ bn1, const float* __restrict__ bn2,
    float* __restrict__ hout, float* __restrict__ cout) {
    __shared__ __nv_bfloat16 Xh[TE][XPAD];
    __shared__ __nv_bfloat16 Xl[TE][XPAD];

    const int tid = threadIdx.x;
    const int lane = tid & 31;
    const int warp = tid >> 5;
    const int rt = warp >> 1;
    const int ct = warp & 1;
    const int g = lane >> 2;
    const int tig = lane & 3;
    const int row0 = rt * 16 + g;
    const int base = blockIdx.x * TE;

    float c[8][4];
#pragma unroll
    for (int nn = 0; nn < 8; nn++)
#pragma unroll
        for (int j = 0; j < 4; j++) c[nn][j] = 0.f;

    for (int i = tid; i < TE * 32; i += 256) {
        int n = base + (i >> 5);
        if (n >= NN) n = NN - 1;
        int l4 = (i & 31) * 4;
        float4 v = __ldg((const float4*)&h[(size_t)n * Dc + l4]);
        __nv_bfloat16 h0, l0, h1, l1, h2, l2, h3, l3;
        splitbf(v.x, h0, l0); splitbf(v.y, h1, l1); splitbf(v.z, h2, l2); splitbf(v.w, h3, l3);
        *(uint2*)&Xh[i >> 5][l4] = make_uint2(pkb(h0, h1), pkb(h2, h3));
        *(uint2*)&Xl[i >> 5][l4] = make_uint2(pkb(l0, l1), pkb(l2, l3));
    }
    __syncthreads();
    gemm_pass<TE>(c, Xh, Xl, 32, rt, ct, lane);  // Wn1 rows [0,128): h part
    __syncthreads();

    for (int i = tid; i < TE * 32; i += 256) {
        int n = base + (i >> 5);
        if (n >= NN) n = NN - 1;
        int l4 = (i & 31) * 4;
        float4 v = *(const float4*)&g_agg[(size_t)n * Dc + l4];
        __nv_bfloat16 h0, l0, h1, l1, h2, l2, h3, l3;
        splitbf(v.x, h0, l0); splitbf(v.y, h1, l1); splitbf(v.z, h2, l2); splitbf(v.w, h3, l3);
        *(uint2*)&Xh[i >> 5][l4] = make_uint2(pkb(h0, h1), pkb(h2, h3));
        *(uint2*)&Xl[i >> 5][l4] = make_uint2(pkb(l0, l1), pkb(l2, l3));
    }
    __syncthreads();
    gemm_pass<TE>(c, Xh, Xl, 40, rt, ct, lane);  // Wn1 rows [128,256): agg part
    __syncthreads();

#pragma unroll
    for (int nn = 0; nn < 8; nn++) {
        int col = ct * 64 + nn * 8 + tig * 2;
        float2 b1 = __ldg((const float2*)&bn1[col]);
        c[nn][0] = siluf_(c[nn][0] + b1.x);
        c[nn][1] = siluf_(c[nn][1] + b1.y);
        c[nn][2] = siluf_(c[nn][2] + b1.x);
        c[nn][3] = siluf_(c[nn][3] + b1.y);
        __nv_bfloat16 h0, l0, h1, l1, h2, l2, h3, l3;
        splitbf(c[nn][0], h0, l0); splitbf(c[nn][1], h1, l1);
        splitbf(c[nn][2], h2, l2); splitbf(c[nn][3], h3, l3);
        *(unsigned*)&Xh[row0][col]     = pkb(h0, h1);
        *(unsigned*)&Xh[row0 + 8][col] = pkb(h2, h3);
        *(unsigned*)&Xl[row0][col]     = pkb(l0, l1);
        *(unsigned*)&Xl[row0 + 8][col] = pkb(l2, l3);
    }
    __syncthreads();

#pragma unroll
    for (int nn = 0; nn < 8; nn++)
#pragma unroll
        for (int j = 0; j < 4; j++) c[nn][j] = 0.f;
    gemm_pass<TE>(c, Xh, Xl, 48, rt, ct, lane);  // Wn2

    {
        int n0 = base + row0, n1 = base + row0 + 8;
#pragma unroll
        for (int nn = 0; nn < 8; nn++) {
            int col = ct * 64 + nn * 8 + tig * 2;
            float2 b2 = __ldg((const float2*)&bn2[col]);
            if (n0 < NN) {
                float2 hv = __ldg((const float2*)&h[(size_t)n0 * Dc + col]);
                *(float2*)&hout[(size_t)n0 * Dc + col] =
                    make_float2(hv.x + c[nn][0] + b2.x, hv.y + c[nn][1] + b2.y);
            }
            if (n1 < NN) {
                float2 hv = __ldg((const float2*)&h[(size_t)n1 * Dc + col]);
                *(float2*)&hout[(size_t)n1 * Dc + col] =
                    make_float2(hv.x + c[nn][2] + b2.x, hv.y + c[nn][3] + b2.y);
            }
        }
    }

    if (tid < TE * 3) {
        int e = tid / 3, cc = tid % 3;
        int n = base + e;
        if (n < NN) {
            float d = fmaxf(g_deg[n], 1.f);
            float v = clampt_(g_csum[(size_t)n * 3 + cc] / d);
            cout[(size_t)n * 3 + cc] = coord[(size_t)n * 3 + cc] + v;
        }
    }
}

extern "C" void kernel_launch(void* const* d_in, const int* in_sizes, int n_in,
                              void* d_out, int out_size) {
    const float* h     = (const float*)d_in[0];
    const int*   ei    = (const int*)d_in[1];   // jax x64 disabled -> int32
    const float* coord = (const float*)d_in[2];
    const float* We1   = (const float*)d_in[3];
    const float* be1   = (const float*)d_in[4];
    const float* We2   = (const float*)d_in[5];
    const float* be2   = (const float*)d_in[6];
    const float* Watt  = (const float*)d_in[7];
    const float* batt  = (const float*)d_in[8];
    const float* Wc1   = (const float*)d_in[9];
    const float* bc1   = (const float*)d_in[10];
    const float* Wc2   = (const float*)d_in[11];
    const float* Wn1   = (const float*)d_in[12];
    const float* bn1   = (const float*)d_in[13];
    const float* Wn2   = (const float*)d_in[14];
    const float* bn2   = (const float*)d_in[15];

    float* out  = (float*)d_out;
    float* hout = out;                                   // [N,128]
    float* cout = out + (size_t)NN * Dc;                 // [N,3]
    float* eout = cout + (size_t)NN * 3;                 // [E,128]

    zero_kernel<<<2048, 256>>>();
    prep_weights<<<(56 * 16 * 32 + 255) / 256, 256>>>(We1, We2, Wc1, Wn1, Wn2);
    pq_kernel<<<(NN + TE - 1) / TE, 256>>>(h);
    edge_kernel<<<(EE + TEE - 1) / TEE, 128>>>(ei, coord, We1, be1,
                                               be2, Watt, batt, bc1, Wc2, eout);
    node_kernel<<<(NN + TE - 1) / TE, 256>>>(h, coord, bn1, bn2, hout, cout);
}

// round 16
// speedup vs baseline: 4.6997x; 1.0848x over previous
#include <cuda_runtime.h>
#include <cuda_bf16.h>
#include <cstdint>

#define Dc 128
#define TE 64          // tile for pq/node kernels (256 threads)
#define TEE 32         // tile for edge kernel (256 threads, 8 warps)
#define NN 50000
#define EE 500000
#define MAXT 10.0f
#define XPAD 136   // bf16 per row: 272B stride -> conflict-free ldmatrix

// Scratch (device globals: no allocation allowed)
__device__ float g_agg[(size_t)NN * Dc];
__device__ float g_csum[(size_t)NN * 3];
__device__ float g_deg[NN];
__device__ float g_P[(size_t)NN * Dc];   // h @ We1[0:128]
__device__ float g_Q[(size_t)NN * Dc];   // h @ We1[128:256]
// Weight fragments: 56 kk-chunks x 16 ntiles x 32 lanes x 16B (hi0,hi1,lo0,lo1)
__device__ uint4 g_wfrag[56 * 16 * 32];

__device__ __forceinline__ float sigmoidf_(float x) { return 1.f / (1.f + __expf(-x)); }
__device__ __forceinline__ float siluf_(float x) { return x / (1.f + __expf(-x)); }
__device__ __forceinline__ float clampt_(float x) { return fminf(fmaxf(x, -MAXT), MAXT); }

__device__ __forceinline__ unsigned pkb(__nv_bfloat16 a, __nv_bfloat16 b) {
    __nv_bfloat162 t(a, b);
    return *(unsigned*)&t;
}
__device__ __forceinline__ void splitbf(float x, __nv_bfloat16& h, __nv_bfloat16& l) {
    h = __float2bfloat16_rn(x);
    l = __float2bfloat16_rn(x - __bfloat162float(h));
}
// vector reduction: one REDG for two adjacent floats (sm_90+)
__device__ __forceinline__ void red2(float* p, float x, float y) {
    asm volatile("red.global.add.v2.f32 [%0], {%1, %2};" :: "l"(p), "f"(x), "f"(y) : "memory");
}

__device__ __forceinline__ void mma16816(float c[4], const unsigned a[4], unsigned b0, unsigned b1) {
    asm volatile(
        "mma.sync.aligned.m16n8k16.row.col.f32.bf16.bf16.f32 "
        "{%0,%1,%2,%3}, {%4,%5,%6,%7}, {%8,%9}, {%0,%1,%2,%3};"
        : "+f"(c[0]), "+f"(c[1]), "+f"(c[2]), "+f"(c[3])
        : "r"(a[0]), "r"(a[1]), "r"(a[2]), "r"(a[3]), "r"(b0), "r"(b1));
}
__device__ __forceinline__ void ldsm4(unsigned r[4], const void* p) {
    uint32_t sa = (uint32_t)__cvta_generic_to_shared(p);
    asm volatile("ldmatrix.sync.aligned.m8n8.x4.shared.b16 {%0,%1,%2,%3}, [%4];"
                 : "=r"(r[0]), "=r"(r[1]), "=r"(r[2]), "=r"(r[3]) : "r"(sa));
}

__global__ void zero_kernel() {
    const int total = NN * Dc + NN * 3 + NN;
    for (int i = blockIdx.x * blockDim.x + threadIdx.x; i < total; i += gridDim.x * blockDim.x) {
        if (i < NN * Dc) g_agg[i] = 0.f;
        else if (i < NN * Dc + NN * 3) g_csum[i - NN * Dc] = 0.f;
        else g_deg[i - NN * Dc - NN * 3] = 0.f;
    }
}

// Pre-split weights into bf16 hi/lo, fragment-major layout.
// kk chunks: We1 rows0-255 -> 0..15 | We2 -> 16..23 | Wc1 -> 24..31 | Wn1 -> 32..47 | Wn2 -> 48..55
__global__ void prep_weights(const float* __restrict__ We1, const float* __restrict__ We2,
                             const float* __restrict__ Wc1, const float* __restrict__ Wn1,
                             const float* __restrict__ Wn2) {
    int idx = blockIdx.x * blockDim.x + threadIdx.x;
    if (idx >= 56 * 16 * 32) return;
    int lane = idx & 31;
    int f = idx >> 5;
    int kk_t = f >> 4;
    int nn_g = f & 15;
    const float* W; int kk;
    if (kk_t < 16)      { W = We1; kk = kk_t; }
    else if (kk_t < 24) { W = We2; kk = kk_t - 16; }
    else if (kk_t < 32) { W = Wc1; kk = kk_t - 24; }
    else if (kk_t < 48) { W = Wn1; kk = kk_t - 32; }
    else                { W = Wn2; kk = kk_t - 48; }
    int n  = nn_g * 8 + (lane >> 2);
    int k0 = kk * 16 + (lane & 3) * 2;
    float v0 = W[(size_t)(k0 + 0) * Dc + n];
    float v1 = W[(size_t)(k0 + 1) * Dc + n];
    float v2 = W[(size_t)(k0 + 8) * Dc + n];
    float v3 = W[(size_t)(k0 + 9) * Dc + n];
    __nv_bfloat16 h0, l0, h1, l1, h2, l2, h3, l3;
    splitbf(v0, h0, l0); splitbf(v1, h1, l1); splitbf(v2, h2, l2); splitbf(v3, h3, l3);
    g_wfrag[f * 32 + lane] = make_uint4(pkb(h0, h1), pkb(h2, h3), pkb(l0, l1), pkb(l2, l3));
}

// Wide pass (pq/node kernels): warp covers 16 rows x 64 cols, c[8][4]
__device__ __forceinline__ void gemm_pass8(float c[8][4],
                                           const __nv_bfloat16 (*Xh)[XPAD],
                                           const __nv_bfloat16 (*Xl)[XPAD],
                                           int wbase, int rt, int ct, int lane) {
    const int arow = rt * 16 + (lane & 15);
    const int acol8 = (lane & 16) >> 1;
#pragma unroll 1
    for (int kk = 0; kk < 8; kk++) {
        unsigned ah[4], al[4];
        ldsm4(ah, &Xh[arow][kk * 16 + acol8]);
        ldsm4(al, &Xl[arow][kk * 16 + acol8]);
        const uint4* wp = &g_wfrag[((size_t)(wbase + kk) * 16 + ct * 8) * 32 + lane];
#pragma unroll
        for (int nn = 0; nn < 8; nn++) {
            uint4 w = __ldg(wp + nn * 32);
            mma16816(c[nn], ah, w.x, w.y);
            mma16816(c[nn], ah, w.z, w.w);
            mma16816(c[nn], al, w.x, w.y);
        }
    }
}

// Narrow pass (edge kernel): warp covers 16 rows x 32 cols, c[4][4] (16 accum regs)
__device__ __forceinline__ void gemm_pass4(float c[4][4],
                                           const __nv_bfloat16 (*Xh)[XPAD],
                                           const __nv_bfloat16 (*Xl)[XPAD],
                                           int wbase, int rt, int ct4, int lane) {
    const int arow = rt * 16 + (lane & 15);
    const int acol8 = (lane & 16) >> 1;
#pragma unroll 1
    for (int kk = 0; kk < 8; kk++) {
        unsigned ah[4], al[4];
        ldsm4(ah, &Xh[arow][kk * 16 + acol8]);
        ldsm4(al, &Xl[arow][kk * 16 + acol8]);
        const uint4* wp = &g_wfrag[((size_t)(wbase + kk) * 16 + ct4 * 4) * 32 + lane];
#pragma unroll
        for (int nn = 0; nn < 4; nn++) {
            uint4 w = __ldg(wp + nn * 32);
            mma16816(c[nn], ah, w.x, w.y);
            mma16816(c[nn], ah, w.z, w.w);
            mma16816(c[nn], al, w.x, w.y);
        }
    }
}

// P = h @ We1_top, Q = h @ We1_bot
__global__ void __launch_bounds__(256) pq_kernel(const float* __restrict__ h) {
    __shared__ __nv_bfloat16 Xh[TE][XPAD];
    __shared__ __nv_bfloat16 Xl[TE][XPAD];
    const int tid = threadIdx.x;
    const int lane = tid & 31;
    const int warp = tid >> 5;
    const int rt = warp >> 1;
    const int ct = warp & 1;
    const int g = lane >> 2;
    const int tig = lane & 3;
    const int row0 = rt * 16 + g;
    const int base = blockIdx.x * TE;

    for (int i = tid; i < TE * 32; i += 256) {
        int n = base + (i >> 5);
        if (n >= NN) n = NN - 1;
        int l4 = (i & 31) * 4;
        float4 v = __ldg((const float4*)&h[(size_t)n * Dc + l4]);
        __nv_bfloat16 h0, l0, h1, l1, h2, l2, h3, l3;
        splitbf(v.x, h0, l0); splitbf(v.y, h1, l1); splitbf(v.z, h2, l2); splitbf(v.w, h3, l3);
        *(uint2*)&Xh[i >> 5][l4] = make_uint2(pkb(h0, h1), pkb(h2, h3));
        *(uint2*)&Xl[i >> 5][l4] = make_uint2(pkb(l0, l1), pkb(l2, l3));
    }
    __syncthreads();

    float c[8][4];
    const int n0 = base + row0, n1 = base + row0 + 8;
#pragma unroll
    for (int nn = 0; nn < 8; nn++)
#pragma unroll
        for (int j = 0; j < 4; j++) c[nn][j] = 0.f;
    gemm_pass8(c, Xh, Xl, 0, rt, ct, lane);     // We1 top
#pragma unroll
    for (int nn = 0; nn < 8; nn++) {
        int col = ct * 64 + nn * 8 + tig * 2;
        if (n0 < NN) *(float2*)&g_P[(size_t)n0 * Dc + col] = make_float2(c[nn][0], c[nn][1]);
        if (n1 < NN) *(float2*)&g_P[(size_t)n1 * Dc + col] = make_float2(c[nn][2], c[nn][3]);
        c[nn][0] = c[nn][1] = c[nn][2] = c[nn][3] = 0.f;
    }
    gemm_pass8(c, Xh, Xl, 8, rt, ct, lane);     // We1 bottom
#pragma unroll
    for (int nn = 0; nn < 8; nn++) {
        int col = ct * 64 + nn * 8 + tig * 2;
        if (n0 < NN) *(float2*)&g_Q[(size_t)n0 * Dc + col] = make_float2(c[nn][0], c[nn][1]);
        if (n1 < NN) *(float2*)&g_Q[(size_t)n1 * Dc + col] = make_float2(c[nn][2], c[nn][3]);
    }
}

// 8 warps: rt = warp>>2 (16-edge half), ct4 = warp&3 (32-col quarter)
__global__ void __launch_bounds__(256, 4) edge_kernel(
    const int* __restrict__ ei, const float* __restrict__ coord,
    const float* __restrict__ We1, const float* __restrict__ be1,
    const float* __restrict__ be2, const float* __restrict__ Watt, const float* __restrict__ batt,
    const float* __restrict__ bc1, const float* __restrict__ Wc2,
    float* __restrict__ edge_out) {
    __shared__ __nv_bfloat16 Xh[TEE][XPAD];
    __shared__ __nv_bfloat16 Xl[TEE][XPAD];
    __shared__ int sRow[TEE];
    __shared__ int sCol[TEE];
    __shared__ float sRad[TEE];
    __shared__ float sCd[TEE][3];
    __shared__ float sPart[4][TEE];

    const int tid = threadIdx.x;
    const int lane = tid & 31;
    const int warp = tid >> 5;
    const int rt = warp >> 2;            // 0..1: 16-edge row tile
    const int ct4 = warp & 3;            // 0..3: 32-col quarter
    const int g = lane >> 2;
    const int tig = lane & 3;
    const int row0 = rt * 16 + g;
    const int base = blockIdx.x * TEE;

    if (tid < TEE) {
        int ee = base + tid;
        if (ee >= EE) ee = EE - 1;  // clamp; writes masked later
        int r = ei[ee];
        int c = ei[EE + ee];
        sRow[tid] = r;
        sCol[tid] = c;
        float dx = coord[r * 3 + 0] - coord[c * 3 + 0];
        float dy = coord[r * 3 + 1] - coord[c * 3 + 1];
        float dz = coord[r * 3 + 2] - coord[c * 3 + 2];
        sCd[tid][0] = dx; sCd[tid][1] = dy; sCd[tid][2] = dz;
        sRad[tid] = dx * dx + dy * dy + dz * dz;
    }
    __syncthreads();

    // ---- layer1 fused: e1 = silu(P[row] + Q[col] + rad*We1[256] + be1); split-stage ----
    for (int i = tid; i < TEE * 32; i += 256) {
        int e = i >> 5, l4 = (i & 31) * 4;
        float4 p = __ldg((const float4*)&g_P[(size_t)sRow[e] * Dc + l4]);
        float4 q = __ldg((const float4*)&g_Q[(size_t)sCol[e] * Dc + l4]);
        float4 wr = __ldg((const float4*)&We1[(size_t)256 * Dc + l4]);
        float4 b1 = __ldg((const float4*)&be1[l4]);
        float rad = sRad[e];
        float v0 = siluf_(p.x + q.x + rad * wr.x + b1.x);
        float v1 = siluf_(p.y + q.y + rad * wr.y + b1.y);
        float v2 = siluf_(p.z + q.z + rad * wr.z + b1.z);
        float v3 = siluf_(p.w + q.w + rad * wr.w + b1.w);
        __nv_bfloat16 h0, l0, h1, l1, h2, l2, h3, l3;
        splitbf(v0, h0, l0); splitbf(v1, h1, l1); splitbf(v2, h2, l2); splitbf(v3, h3, l3);
        *(uint2*)&Xh[e][l4] = make_uint2(pkb(h0, h1), pkb(h2, h3));
        *(uint2*)&Xl[e][l4] = make_uint2(pkb(l0, l1), pkb(l2, l3));
    }
    __syncthreads();

    // ---- layer2: e2 = silu(e1@We2+be2); att; ef = e2*att ----
    float c[4][4];
#pragma unroll
    for (int nn = 0; nn < 4; nn++)
#pragma unroll
        for (int j = 0; j < 4; j++) c[nn][j] = 0.f;
    gemm_pass4(c, Xh, Xl, 16, rt, ct4, lane);

    {
        float pA = 0.f, pB = 0.f;
#pragma unroll
        for (int nn = 0; nn < 4; nn++) {
            int col = ct4 * 32 + nn * 8 + tig * 2;
            float2 b2 = __ldg((const float2*)&be2[col]);
            float2 wa = __ldg((const float2*)&Watt[col]);
            c[nn][0] = siluf_(c[nn][0] + b2.x);
            c[nn][1] = siluf_(c[nn][1] + b2.y);
            c[nn][2] = siluf_(c[nn][2] + b2.x);
            c[nn][3] = siluf_(c[nn][3] + b2.y);
            pA += c[nn][0] * wa.x + c[nn][1] * wa.y;
            pB += c[nn][2] * wa.x + c[nn][3] * wa.y;
        }
        pA += __shfl_xor_sync(0xffffffffu, pA, 1); pA += __shfl_xor_sync(0xffffffffu, pA, 2);
        pB += __shfl_xor_sync(0xffffffffu, pB, 1); pB += __shfl_xor_sync(0xffffffffu, pB, 2);
        if (tig == 0) { sPart[ct4][row0] = pA; sPart[ct4][row0 + 8] = pB; }
    }
    __syncthreads();
    {
        float ba = __ldg(batt);
        float attA = sigmoidf_(sPart[0][row0] + sPart[1][row0] + sPart[2][row0] + sPart[3][row0] + ba);
        float attB = sigmoidf_(sPart[0][row0 + 8] + sPart[1][row0 + 8] + sPart[2][row0 + 8] + sPart[3][row0 + 8] + ba);
#pragma unroll
        for (int nn = 0; nn < 4; nn++) {
            c[nn][0] *= attA; c[nn][1] *= attA;
            c[nn][2] *= attB; c[nn][3] *= attB;
        }
    }
    __syncthreads();

    // ---- write edge_feat, agg reductions (v2), restage ef for coord MLP ----
    {
        int r0 = sRow[row0], r1 = sRow[row0 + 8];
        int ee0 = base + row0, ee1 = base + row0 + 8;
#pragma unroll
        for (int nn = 0; nn < 4; nn++) {
            int col = ct4 * 32 + nn * 8 + tig * 2;
            __nv_bfloat16 h0, l0, h1, l1, h2, l2, h3, l3;
            splitbf(c[nn][0], h0, l0); splitbf(c[nn][1], h1, l1);
            splitbf(c[nn][2], h2, l2); splitbf(c[nn][3], h3, l3);
            *(unsigned*)&Xh[row0][col]     = pkb(h0, h1);
            *(unsigned*)&Xh[row0 + 8][col] = pkb(h2, h3);
            *(unsigned*)&Xl[row0][col]     = pkb(l0, l1);
            *(unsigned*)&Xl[row0 + 8][col] = pkb(l2, l3);
            if (ee0 < EE) {
                *(float2*)&edge_out[(size_t)ee0 * Dc + col] = make_float2(c[nn][0], c[nn][1]);
                red2(&g_agg[(size_t)r0 * Dc + col], c[nn][0], c[nn][1]);
            }
            if (ee1 < EE) {
                *(float2*)&edge_out[(size_t)ee1 * Dc + col] = make_float2(c[nn][2], c[nn][3]);
                red2(&g_agg[(size_t)r1 * Dc + col], c[nn][2], c[nn][3]);
            }
        }
    }
    __syncthreads();

    // ---- coord MLP: cw = silu(ef@Wc1+bc1) @ Wc2 ----
#pragma unroll
    for (int nn = 0; nn < 4; nn++)
#pragma unroll
        for (int j = 0; j < 4; j++) c[nn][j] = 0.f;
    gemm_pass4(c, Xh, Xl, 24, rt, ct4, lane);

    {
        float pA = 0.f, pB = 0.f;
#pragma unroll
        for (int nn = 0; nn < 4; nn++) {
            int col = ct4 * 32 + nn * 8 + tig * 2;
            float2 bc = __ldg((const float2*)&bc1[col]);
            float2 w2 = __ldg((const float2*)&Wc2[col]);
            pA += siluf_(c[nn][0] + bc.x) * w2.x + siluf_(c[nn][1] + bc.y) * w2.y;
            pB += siluf_(c[nn][2] + bc.x) * w2.x + siluf_(c[nn][3] + bc.y) * w2.y;
        }
        pA += __shfl_xor_sync(0xffffffffu, pA, 1); pA += __shfl_xor_sync(0xffffffffu, pA, 2);
        pB += __shfl_xor_sync(0xffffffffu, pB, 1); pB += __shfl_xor_sync(0xffffffffu, pB, 2);
        if (tig == 0) { sPart[ct4][row0] = pA; sPart[ct4][row0 + 8] = pB; }
    }
    __syncthreads();
    if (ct4 == 0) {
#pragma unroll
        for (int half = 0; half < 2; half++) {
            int rr = row0 + half * 8;
            int ee = base + rr;
            if (ee < EE) {
                float cw = sPart[0][rr] + sPart[1][rr] + sPart[2][rr] + sPart[3][rr];
                if (tig < 3) {
                    float t = clampt_(sCd[rr][tig] * cw);
                    atomicAdd(&g_csum[(size_t)sRow[rr] * 3 + tig], t);
                } else {
                    atomicAdd(&g_deg[sRow[rr]], 1.f);
                }
            }
        }
    }
}

__global__ void __launch_bounds__(256) node_kernel(
    const float* __restrict__ h, const float* __restrict__ coord,
    const float* __restrict__ bn1, const float* __restrict__ bn2,
    float* __restrict__ hout, float* __restrict__ cout) {
    __shared__ __nv_bfloat16 Xh[TE][XPAD];
    __shared__ __nv_bfloat16 Xl[TE][XPAD];

    const int tid = threadIdx.x;
    const int lane = tid & 31;
    const int warp = tid >> 5;
    const int rt = warp >> 1;
    const int ct = warp & 1;
    const int g = lane >> 2;
    const int tig = lane & 3;
    const int row0 = rt * 16 + g;
    const int base = blockIdx.x * TE;

    float c[8][4];
#pragma unroll
    for (int nn = 0; nn < 8; nn++)
#pragma unroll
        for (int j = 0; j < 4; j++) c[nn][j] = 0.f;

    for (int i = tid; i < TE * 32; i += 256) {
        int n = base + (i >> 5);
        if (n >= NN) n = NN - 1;
        int l4 = (i & 31) * 4;
        float4 v = __ldg((const float4*)&h[(size_t)n * Dc + l4]);
        __nv_bfloat16 h0, l0, h1, l1, h2, l2, h3, l3;
        splitbf(v.x, h0, l0); splitbf(v.y, h1, l1); splitbf(v.z, h2, l2); splitbf(v.w, h3, l3);
        *(uint2*)&Xh[i >> 5][l4] = make_uint2(pkb(h0, h1), pkb(h2, h3));
        *(uint2*)&Xl[i >> 5][l4] = make_uint2(pkb(l0, l1), pkb(l2, l3));
    }
    __syncthreads();
    gemm_pass8(c, Xh, Xl, 32, rt, ct, lane);  // Wn1 rows [0,128): h part
    __syncthreads();

    for (int i = tid; i < TE * 32; i += 256) {
        int n = base + (i >> 5);
        if (n >= NN) n = NN - 1;
        int l4 = (i & 31) * 4;
        float4 v = *(const float4*)&g_agg[(size_t)n * Dc + l4];
        __nv_bfloat16 h0, l0, h1, l1, h2, l2, h3, l3;
        splitbf(v.x, h0, l0); splitbf(v.y, h1, l1); splitbf(v.z, h2, l2); splitbf(v.w, h3, l3);
        *(uint2*)&Xh[i >> 5][l4] = make_uint2(pkb(h0, h1), pkb(h2, h3));
        *(uint2*)&Xl[i >> 5][l4] = make_uint2(pkb(l0, l1), pkb(l2, l3));
    }
    __syncthreads();
    gemm_pass8(c, Xh, Xl, 40, rt, ct, lane);  // Wn1 rows [128,256): agg part
    __syncthreads();

#pragma unroll
    for (int nn = 0; nn < 8; nn++) {
        int col = ct * 64 + nn * 8 + tig * 2;
        float2 b1 = __ldg((const float2*)&bn1[col]);
        c[nn][0] = siluf_(c[nn][0] + b1.x);
        c[nn][1] = siluf_(c[nn][1] + b1.y);
        c[nn][2] = siluf_(c[nn][2] + b1.x);
        c[nn][3] = siluf_(c[nn][3] + b1.y);
        __nv_bfloat16 h0, l0, h1, l1, h2, l2, h3, l3;
        splitbf(c[nn][0], h0, l0); splitbf(c[nn][1], h1, l1);
        splitbf(c[nn][2], h2, l2); splitbf(c[nn][3], h3, l3);
        *(unsigned*)&Xh[row0][col]     = pkb(h0, h1);
        *(unsigned*)&Xh[row0 + 8][col] = pkb(h2, h3);
        *(unsigned*)&Xl[row0][col]     = pkb(l0, l1);
        *(unsigned*)&Xl[row0 + 8][col] = pkb(l2, l3);
    }
    __syncthreads();

#pragma unroll
    for (int nn = 0; nn < 8; nn++)
#pragma unroll
        for (int j = 0; j < 4; j++) c[nn][j] = 0.f;
    gemm_pass8(c, Xh, Xl, 48, rt, ct, lane);  // Wn2

    {
        int n0 = base + row0, n1 = base + row0 + 8;
#pragma unroll
        for (int nn = 0; nn < 8; nn++) {
            int col = ct * 64 + nn * 8 + tig * 2;
            float2 b2 = __ldg((const float2*)&bn2[col]);
            if (n0 < NN) {
                float2 hv = __ldg((const float2*)&h[(size_t)n0 * Dc + col]);
                *(float2*)&hout[(size_t)n0 * Dc + col] =
                    make_float2(hv.x + c[nn][0] + b2.x, hv.y + c[nn][1] + b2.y);
            }
            if (n1 < NN) {
                float2 hv = __ldg((const float2*)&h[(size_t)n1 * Dc + col]);
                *(float2*)&hout[(size_t)n1 * Dc + col] =
                    make_float2(hv.x + c[nn][2] + b2.x, hv.y + c[nn][3] + b2.y);
            }
        }
    }

    if (tid < TE * 3) {
        int e = tid / 3, cc = tid % 3;
        int n = base + e;
        if (n < NN) {
            float d = fmaxf(g_deg[n], 1.f);
            float v = clampt_(g_csum[(size_t)n * 3 + cc] / d);
            cout[(size_t)n * 3 + cc] = coord[(size_t)n * 3 + cc] + v;
        }
    }
}

extern "C" void kernel_launch(void* const* d_in, const int* in_sizes, int n_in,
                              void* d_out, int out_size) {
    const float* h     = (const float*)d_in[0];
    const int*   ei    = (const int*)d_in[1];   // jax x64 disabled -> int32
    const float* coord = (const float*)d_in[2];
    const float* We1   = (const float*)d_in[3];
    const float* be1   = (const float*)d_in[4];
    const float* We2   = (const float*)d_in[5];
    const float* be2   = (const float*)d_in[6];
    const float* Watt  = (const float*)d_in[7];
    const float* batt  = (const float*)d_in[8];
    const float* Wc1   = (const float*)d_in[9];
    const float* bc1   = (const float*)d_in[10];
    const float* Wc2   = (const float*)d_in[11];
    const float* Wn1   = (const float*)d_in[12];
    const float* bn1   = (const float*)d_in[13];
    const float* Wn2   = (const float*)d_in[14];
    const float* bn2   = (const float*)d_in[15];

    float* out  = (float*)d_out;
    float* hout = out;                                   // [N,128]
    float* cout = out + (size_t)NN * Dc;                 // [N,3]
    float* eout = cout + (size_t)NN * 3;                 // [E,128]

    zero_kernel<<<2048, 256>>>();
    prep_weights<<<(56 * 16 * 32 + 255) / 256, 256>>>(We1, We2, Wc1, Wn1, Wn2);
    pq_kernel<<<(NN + TE - 1) / TE, 256>>>(h);
    edge_kernel<<<(EE + TEE - 1) / TEE, 256>>>(ei, coord, We1, be1,
                                               be2, Watt, batt, bc1, Wc2, eout);
    node_kernel<<<(NN + TE - 1) / TE, 256>>>(h, coord, bn1, bn2, hout, cout);
}